// round 7
// baseline (speedup 1.0000x reference)
#include <cuda_runtime.h>
#include <mma.h>
#include <math.h>
#include <stdint.h>

using namespace nvcuda;

#define T  1024
#define Hd 1024
#define Fd 2048
#define Ed 8

#define BM 128
#define BN 64
#define BK 16
#define KP 20                  // BK + 4 pad floats
#define RB (KP * 4)            // 80 B per row
#define A_BYTES (BM * RB)      // 10240
#define B_BYTES (BN * RB)      // 5120
#define NSTAGE 3
#define OPAD 68

#define F1_A   1024
#define F1_B1  (F1_A  + NSTAGE * A_BYTES)
#define F1_B3  (F1_B1 + NSTAGE * B_BYTES)
#define SMEM_FFN1 (F1_B3 + NSTAGE * B_BYTES)
#define F2_A   1024
#define F2_B   (F2_A + NSTAGE * A_BYTES)
#define SMEM_FFN2 (F2_B + NSTAGE * B_BYTES)

// ---------------- scratch ----------------
__device__ float g_inter[(size_t)Ed * T * Fd];           // 64 MB (tf32-rounded)
__device__ float g_w1c[(size_t)Ed * Fd * Hd];            // 64 MB tf32-rounded w1
__device__ float g_w3c[(size_t)Ed * Fd * Hd];            // 64 MB tf32-rounded w3
__device__ float g_w2c[(size_t)Ed * Hd * Fd];            // 64 MB tf32-rounded w2
__device__ float g_xc[(size_t)T * Hd];                   // 4 MB tf32-rounded x
__device__ int   g_tok[Ed * T];
__device__ float g_pw[Ed * T];
__device__ int   g_cnt[Ed];
__device__ int   g_sel[T * 2];
__device__ float g_mult[T * 2];

__device__ __forceinline__ float tf32r(float x) {
    float r; asm("cvt.rna.tf32.f32 %0, %1;" : "=f"(r) : "f"(x)); return r;
}
__device__ __forceinline__ void cp16(void* s, const float* g) {
    unsigned a = (unsigned)__cvta_generic_to_shared(s);
    asm volatile("cp.async.cg.shared.global [%0], [%1], 16;" :: "r"(a), "l"(g));
}
#define CP_COMMIT() asm volatile("cp.async.commit_group;" ::)
#define CP_WAIT1()  asm volatile("cp.async.wait_group 1;" ::)

// ---------------- kernel 0: zero output + counters ----------------
__global__ void zero_kernel(float* __restrict__ out) {
    int i = blockIdx.x * 256 + threadIdx.x;
    out[i] = 0.0f;
    if (i < Ed) g_cnt[i] = 0;
}

// ---------------- kernel 0b: tf32 pre-round (vectorized) ----------------
__global__ __launch_bounds__(256) void cvt_kernel(const float4* __restrict__ src,
                                                  float4* __restrict__ dst) {
    size_t i = (size_t)blockIdx.x * 256 + threadIdx.x;
    float4 v = src[i];
    v.x = tf32r(v.x); v.y = tf32r(v.y); v.z = tf32r(v.z); v.w = tf32r(v.w);
    dst[i] = v;
}

// ---------------- kernel 1: router ----------------
__global__ __launch_bounds__(256) void router_kernel(
    const float* __restrict__ x, const float* __restrict__ gw,
    float* __restrict__ out_logits, int write_logits)
{
    int t = blockIdx.x, warp = threadIdx.x >> 5, lane = threadIdx.x & 31;
    const float* xr = x + (size_t)t * Hd;
    const float* gr = gw + (size_t)warp * Hd;
    float s = 0.0f;
    for (int h = lane; h < Hd; h += 32) s += xr[h] * gr[h];
    #pragma unroll
    for (int o = 16; o; o >>= 1) s += __shfl_xor_sync(0xFFFFFFFFu, s, o);

    __shared__ float sc[Ed];
    if (lane == 0) sc[warp] = s;
    __syncthreads();
    if (threadIdx.x < Ed && write_logits) out_logits[t * Ed + threadIdx.x] = sc[threadIdx.x];

    if (threadIdx.x == 0) {
        float v[Ed];
        #pragma unroll
        for (int e = 0; e < Ed; e++) v[e] = sc[e];
        int s1 = 0; float m1 = v[0];
        #pragma unroll
        for (int e = 1; e < Ed; e++) if (v[e] > m1) { m1 = v[e]; s1 = e; }
        float Z1 = 0.0f;
        #pragma unroll
        for (int e = 0; e < Ed; e++) {
            float factor = fmaxf(fabsf(v[e]), m1);
            if (!((m1 - v[e]) / factor > 0.02f)) Z1 += expf(v[e] - m1);
        }
        int s2 = -1; float m2 = -INFINITY;
        #pragma unroll
        for (int e = 0; e < Ed; e++) if (e != s1 && v[e] > m2) { m2 = v[e]; s2 = e; }
        float Z2 = 0.0f;
        #pragma unroll
        for (int e = 0; e < Ed; e++) {
            if (e == s1) continue;
            float factor = fmaxf(fabsf(v[e]), m2);
            if (!((m2 - v[e]) / factor > 0.02f)) Z2 += expf(v[e] - m2);
        }
        g_sel [t * 2 + 0] = s1;        g_sel [t * 2 + 1] = s2;
        g_mult[t * 2 + 0] = 1.0f / Z1; g_mult[t * 2 + 1] = 1.0f / Z2;
    }
}

// ---------------- kernel 2: scatter ----------------
__global__ void scatter_kernel() {
    int t = blockIdx.x * 256 + threadIdx.x;
    if (t >= T) return;
    #pragma unroll
    for (int k = 0; k < 2; k++) {
        int e = g_sel[t * 2 + k];
        int p = atomicAdd(&g_cnt[e], 1);
        g_tok[e * T + p] = t;
        g_pw [e * T + p] = g_mult[t * 2 + k];
    }
}

// ---------------- kernel 3: ffn1 (no cvt in loop) ---------------------------
// grid (Fd/BN=32, Ed*8=64), 256 threads (8 warps, 4m x 2n), warp 32x32 dual
__global__ __launch_bounds__(256, 2) void ffn1_kernel()
{
    extern __shared__ char sm[];
    int e   = blockIdx.y >> 3;
    int mt  = blockIdx.y & 7;
    int cnt = g_cnt[e];
    int m0  = mt * BM;
    if (m0 >= cnt) return;
    int f0  = blockIdx.x * BN;

    int* toks = (int*)sm;
    int tid = threadIdx.x;
    if (tid < BM) {
        int i = m0 + tid;
        toks[tid] = (i < cnt) ? g_tok[e * T + i] : g_tok[e * T];
    }
    __syncthreads();

    int ar0 = tid >> 2;
    int aq  = (tid & 3) * 4;
    uint32_t soA0 = (uint32_t)ar0 * RB + aq * 4;
    uint32_t soA1 = soA0 + 64 * RB;
    uint32_t soB  = soA0;

    const float* w1e = g_w1c + (size_t)e * Fd * Hd;
    const float* w3e = g_w3c + (size_t)e * Fd * Hd;
    const float* ag0 = g_xc + (size_t)toks[ar0]      * Hd + aq;
    const float* ag1 = g_xc + (size_t)toks[ar0 + 64] * Hd + aq;
    const float* b1g = w1e + (size_t)(f0 + ar0) * Hd + aq;
    const float* b3g = w3e + (size_t)(f0 + ar0) * Hd + aq;

    char* smA  = sm + F1_A;
    char* smB1 = sm + F1_B1;
    char* smB3 = sm + F1_B3;

    #pragma unroll
    for (int s = 0; s < NSTAGE - 1; s++) {
        int k0 = s * BK;
        cp16(smA  + s * A_BYTES + soA0, ag0 + k0);
        cp16(smA  + s * A_BYTES + soA1, ag1 + k0);
        cp16(smB1 + s * B_BYTES + soB,  b1g + k0);
        cp16(smB3 + s * B_BYTES + soB,  b3g + k0);
        CP_COMMIT();
    }

    wmma::fragment<wmma::matrix_a, 16,16,8, wmma::precision::tf32, wmma::row_major> fa[2];
    wmma::fragment<wmma::matrix_b, 16,16,8, wmma::precision::tf32, wmma::col_major> fb1[2], fb3[2];
    wmma::fragment<wmma::accumulator, 16,16,8, float> acc1[2][2], acc3[2][2];
    #pragma unroll
    for (int i = 0; i < 2; i++)
        #pragma unroll
        for (int j = 0; j < 2; j++) { wmma::fill_fragment(acc1[i][j], 0.f); wmma::fill_fragment(acc3[i][j], 0.f); }

    int wid = tid >> 5;
    int wm  = wid >> 1;
    int wn  = wid & 1;

    int cur = 0, nxt = NSTAGE - 1;
    const int NS = Hd / BK;
    for (int s = 0; s < NS; s++) {
        CP_WAIT1();
        __syncthreads();
        if (s + NSTAGE - 1 < NS) {
            int k0 = (s + NSTAGE - 1) * BK;
            cp16(smA  + nxt * A_BYTES + soA0, ag0 + k0);
            cp16(smA  + nxt * A_BYTES + soA1, ag1 + k0);
            cp16(smB1 + nxt * B_BYTES + soB,  b1g + k0);
            cp16(smB3 + nxt * B_BYTES + soB,  b3g + k0);
        }
        CP_COMMIT();

        const float* Ab  = (const float*)(smA  + cur * A_BYTES);
        const float* B1b = (const float*)(smB1 + cur * B_BYTES);
        const float* B3b = (const float*)(smB3 + cur * B_BYTES);
        #pragma unroll
        for (int ks = 0; ks < BK; ks += 8) {
            wmma::load_matrix_sync(fa[0],  Ab  + (wm*32     ) * KP + ks, KP);
            wmma::load_matrix_sync(fa[1],  Ab  + (wm*32 + 16) * KP + ks, KP);
            wmma::load_matrix_sync(fb1[0], B1b + (wn*32     ) * KP + ks, KP);
            wmma::load_matrix_sync(fb1[1], B1b + (wn*32 + 16) * KP + ks, KP);
            wmma::load_matrix_sync(fb3[0], B3b + (wn*32     ) * KP + ks, KP);
            wmma::load_matrix_sync(fb3[1], B3b + (wn*32 + 16) * KP + ks, KP);
            #pragma unroll
            for (int i = 0; i < 2; i++)
                #pragma unroll
                for (int j = 0; j < 2; j++) {
                    wmma::mma_sync(acc1[i][j], fa[i], fb1[j], acc1[i][j]);
                    wmma::mma_sync(acc3[i][j], fa[i], fb3[j], acc3[i][j]);
                }
        }
        cur = (cur + 1 == NSTAGE) ? 0 : cur + 1;
        nxt = (nxt + 1 == NSTAGE) ? 0 : nxt + 1;
    }

    // epilogue: tf32-rounded silu(h1)*h3 -> g_inter (pre-rounded for ffn2)
    float* ob = &g_inter[((size_t)e * T + m0 + wm*32) * Fd + f0 + wn*32];
    #pragma unroll
    for (int i = 0; i < 2; i++)
        #pragma unroll
        for (int j = 0; j < 2; j++) {
            #pragma unroll
            for (int el = 0; el < acc1[i][j].num_elements; el++) {
                float h1 = acc1[i][j].x[el], h3 = acc3[i][j].x[el];
                acc1[i][j].x[el] = tf32r(h1 / (1.0f + expf(-h1)) * h3);
            }
            wmma::store_matrix_sync(ob + (size_t)i*16*Fd + j*16, acc1[i][j], Fd, wmma::mem_row_major);
        }
}

// ---------------- kernel 4: ffn2 (no cvt in loop) ---------------------------
// grid (Hd/BN=16, Ed*8=64), 256 threads, warp 32x32
__global__ __launch_bounds__(256, 2) void ffn2_kernel(float* __restrict__ out)
{
    extern __shared__ char sm[];
    int e   = blockIdx.y >> 3;
    int mt  = blockIdx.y & 7;
    int cnt = g_cnt[e];
    int m0  = mt * BM;
    if (m0 >= cnt) return;
    int h0  = blockIdx.x * BN;

    int*   toks = (int*)sm;
    float* pws  = (float*)(sm + 512);
    int tid = threadIdx.x;
    if (tid < BM) {
        int i = m0 + tid;
        toks[tid] = (i < cnt) ? g_tok[e * T + i] : 0;
        pws [tid] = (i < cnt) ? g_pw [e * T + i] : 0.0f;
    }
    __syncthreads();

    int ar0 = tid >> 2;
    int aq  = (tid & 3) * 4;
    uint32_t soA0 = (uint32_t)ar0 * RB + aq * 4;
    uint32_t soA1 = soA0 + 64 * RB;
    uint32_t soB  = soA0;

    const float* ag0 = &g_inter[((size_t)e * T + m0 + ar0     ) * Fd + aq];
    const float* ag1 = &g_inter[((size_t)e * T + m0 + ar0 + 64) * Fd + aq];
    const float* bg  = g_w2c + ((size_t)e * Hd + h0 + ar0) * Fd + aq;

    char* smA = sm + F2_A;
    char* smB = sm + F2_B;

    #pragma unroll
    for (int s = 0; s < NSTAGE - 1; s++) {
        int k0 = s * BK;
        cp16(smA + s * A_BYTES + soA0, ag0 + k0);
        cp16(smA + s * A_BYTES + soA1, ag1 + k0);
        cp16(smB + s * B_BYTES + soB,  bg  + k0);
        CP_COMMIT();
    }

    wmma::fragment<wmma::matrix_a, 16,16,8, wmma::precision::tf32, wmma::row_major> fa[2];
    wmma::fragment<wmma::matrix_b, 16,16,8, wmma::precision::tf32, wmma::col_major> fb[2];
    wmma::fragment<wmma::accumulator, 16,16,8, float> acc[2][2];
    #pragma unroll
    for (int i = 0; i < 2; i++)
        #pragma unroll
        for (int j = 0; j < 2; j++) wmma::fill_fragment(acc[i][j], 0.f);

    int wid = tid >> 5;
    int wm  = wid >> 1;
    int wn  = wid & 1;

    int cur = 0, nxt = NSTAGE - 1;
    const int NS = Fd / BK;
    for (int s = 0; s < NS; s++) {
        CP_WAIT1();
        __syncthreads();
        if (s + NSTAGE - 1 < NS) {
            int k0 = (s + NSTAGE - 1) * BK;
            cp16(smA + nxt * A_BYTES + soA0, ag0 + k0);
            cp16(smA + nxt * A_BYTES + soA1, ag1 + k0);
            cp16(smB + nxt * B_BYTES + soB,  bg  + k0);
        }
        CP_COMMIT();

        const float* Ab = (const float*)(smA + cur * A_BYTES);
        const float* Bb = (const float*)(smB + cur * B_BYTES);
        #pragma unroll
        for (int ks = 0; ks < BK; ks += 8) {
            wmma::load_matrix_sync(fa[0], Ab + (wm*32     ) * KP + ks, KP);
            wmma::load_matrix_sync(fa[1], Ab + (wm*32 + 16) * KP + ks, KP);
            wmma::load_matrix_sync(fb[0], Bb + (wn*32     ) * KP + ks, KP);
            wmma::load_matrix_sync(fb[1], Bb + (wn*32 + 16) * KP + ks, KP);
            #pragma unroll
            for (int i = 0; i < 2; i++)
                #pragma unroll
                for (int j = 0; j < 2; j++)
                    wmma::mma_sync(acc[i][j], fa[i], fb[j], acc[i][j]);
        }
        cur = (cur + 1 == NSTAGE) ? 0 : cur + 1;
        nxt = (nxt + 1 == NSTAGE) ? 0 : nxt + 1;
    }

    __syncthreads();
    float* pool = (float*)(sm + F2_A);
    #pragma unroll
    for (int i = 0; i < 2; i++)
        #pragma unroll
        for (int j = 0; j < 2; j++)
            wmma::store_matrix_sync(
                pool + (size_t)(wm*32 + i*16) * OPAD + wn*32 + j*16,
                acc[i][j], OPAD, wmma::mem_row_major);
    __syncthreads();

    for (int idx = tid; idx < BM * BN; idx += 256) {
        int r = idx >> 6;
        int c = idx & 63;
        if (m0 + r < cnt)
            atomicAdd(&out[(size_t)toks[r] * Hd + h0 + c], pws[r] * pool[r * OPAD + c]);
    }
}

// ---------------- launch ----------------
extern "C" void kernel_launch(void* const* d_in, const int* in_sizes, int n_in,
                              void* d_out, int out_size)
{
    const float* x  = (const float*)d_in[0];
    const float* gw = (const float*)d_in[1];
    const float* w1 = (const float*)d_in[2];
    const float* w2 = (const float*)d_in[3];
    const float* w3 = (const float*)d_in[4];
    float* out = (float*)d_out;

    cudaFuncSetAttribute(ffn1_kernel, cudaFuncAttributeMaxDynamicSharedMemorySize, SMEM_FFN1);
    cudaFuncSetAttribute(ffn2_kernel, cudaFuncAttributeMaxDynamicSharedMemorySize, SMEM_FFN2);

    int write_logits = (out_size >= T * Hd + T * Ed) ? 1 : 0;
    float* out_logits = out + (size_t)T * Hd;

    float *d_w1c, *d_w3c, *d_w2c, *d_xc;
    cudaGetSymbolAddress((void**)&d_w1c, g_w1c);
    cudaGetSymbolAddress((void**)&d_w3c, g_w3c);
    cudaGetSymbolAddress((void**)&d_w2c, g_w2c);
    cudaGetSymbolAddress((void**)&d_xc,  g_xc);

    zero_kernel   <<<(T * Hd) / 256, 256>>>(out);
    router_kernel <<<T, 256>>>(x, gw, out_logits, write_logits);
    scatter_kernel<<<T / 256, 256>>>();

    // tf32 pre-round: x + all weights (memory-bound; removes cvt from ffn loops)
    const size_t WN = (size_t)Ed * Fd * Hd / 4;   // float4 count per weight
    cvt_kernel<<<(T * Hd / 4) / 256, 256>>>((const float4*)x,  (float4*)d_xc);
    cvt_kernel<<<(int)(WN / 256), 256>>>((const float4*)w1, (float4*)d_w1c);
    cvt_kernel<<<(int)(WN / 256), 256>>>((const float4*)w3, (float4*)d_w3c);
    cvt_kernel<<<(int)(WN / 256), 256>>>((const float4*)w2, (float4*)d_w2c);

    dim3 g1(Fd / BN, Ed * 8);
    ffn1_kernel<<<g1, 256, SMEM_FFN1>>>();

    dim3 g2(Hd / BN, Ed * 8);
    ffn2_kernel<<<g2, 256, SMEM_FFN2>>>(out);
}

// round 8
// speedup vs baseline: 2.7650x; 2.7650x over previous
#include <cuda_runtime.h>
#include <cuda_fp16.h>
#include <mma.h>
#include <math.h>
#include <stdint.h>

using namespace nvcuda;

#define T  1024
#define Hd 1024
#define Fd 2048
#define Ed 8

#define BM 128
#define BN 64
#define BK 32                  // halves; 64B per row per stage
#define KP 40                  // BK + 8 pad halves -> 80B rows
#define RB 80
#define A_BYTES (BM * RB)      // 10240
#define B_BYTES (BN * RB)      // 5120
#define NSTAGE 3
#define OPAD 68

#define F1_A   1024
#define F1_B1  (F1_A  + NSTAGE * A_BYTES)
#define F1_B3  (F1_B1 + NSTAGE * B_BYTES)
#define SMEM_FFN1 (F1_B3 + NSTAGE * B_BYTES)   // 62464
#define F2_A   1024
#define F2_B   (F2_A + NSTAGE * A_BYTES)
#define SMEM_FFN2 (F2_B + NSTAGE * B_BYTES)    // 47104

// ---------------- scratch ----------------
__device__ __half g_interh[(size_t)Ed * T * Fd];         // 32 MB
__device__ __half g_w1h[(size_t)Ed * Fd * Hd];           // 32 MB
__device__ __half g_w3h[(size_t)Ed * Fd * Hd];           // 32 MB
__device__ __half g_w2h[(size_t)Ed * Hd * Fd];           // 32 MB
__device__ __half g_xh[(size_t)T * Hd];                  // 2 MB
__device__ int   g_tok[Ed * T];
__device__ float g_pw[Ed * T];
__device__ int   g_cnt[Ed];
__device__ int   g_sel[T * 2];
__device__ float g_mult[T * 2];

__device__ __forceinline__ uint32_t f2h2(float x, float y) {
    __half2 h = __floats2half2_rn(x, y);
    return *(uint32_t*)&h;
}
__device__ __forceinline__ void cp16(void* s, const void* g) {
    unsigned a = (unsigned)__cvta_generic_to_shared(s);
    asm volatile("cp.async.cg.shared.global [%0], [%1], 16;" :: "r"(a), "l"(g));
}
#define CP_COMMIT() asm volatile("cp.async.commit_group;" ::)
#define CP_WAIT1()  asm volatile("cp.async.wait_group 1;" ::)

// ---------------- kernel 0: zero output + counters ----------------
__global__ void zero_kernel(float* __restrict__ out) {
    int i = blockIdx.x * 256 + threadIdx.x;
    out[i] = 0.0f;
    if (i < Ed) g_cnt[i] = 0;
}

// ---------------- kernel 0b: fp32 -> fp16 convert (8 floats/thread) --------
__global__ __launch_bounds__(256) void cvt_h_kernel(const float4* __restrict__ src,
                                                    uint4* __restrict__ dst) {
    size_t i = (size_t)blockIdx.x * 256 + threadIdx.x;
    float4 a = src[2 * i];
    float4 b = src[2 * i + 1];
    uint4 o;
    o.x = f2h2(a.x, a.y);
    o.y = f2h2(a.z, a.w);
    o.z = f2h2(b.x, b.y);
    o.w = f2h2(b.z, b.w);
    dst[i] = o;
}

// ---------------- kernel 1: router (fp32, unchanged numerics) --------------
__global__ __launch_bounds__(256) void router_kernel(
    const float* __restrict__ x, const float* __restrict__ gw,
    float* __restrict__ out_logits, int write_logits)
{
    int t = blockIdx.x, warp = threadIdx.x >> 5, lane = threadIdx.x & 31;
    const float* xr = x + (size_t)t * Hd;
    const float* gr = gw + (size_t)warp * Hd;
    float s = 0.0f;
    for (int h = lane; h < Hd; h += 32) s += xr[h] * gr[h];
    #pragma unroll
    for (int o = 16; o; o >>= 1) s += __shfl_xor_sync(0xFFFFFFFFu, s, o);

    __shared__ float sc[Ed];
    if (lane == 0) sc[warp] = s;
    __syncthreads();
    if (threadIdx.x < Ed && write_logits) out_logits[t * Ed + threadIdx.x] = sc[threadIdx.x];

    if (threadIdx.x == 0) {
        float v[Ed];
        #pragma unroll
        for (int e = 0; e < Ed; e++) v[e] = sc[e];
        int s1 = 0; float m1 = v[0];
        #pragma unroll
        for (int e = 1; e < Ed; e++) if (v[e] > m1) { m1 = v[e]; s1 = e; }
        float Z1 = 0.0f;
        #pragma unroll
        for (int e = 0; e < Ed; e++) {
            float factor = fmaxf(fabsf(v[e]), m1);
            if (!((m1 - v[e]) / factor > 0.02f)) Z1 += expf(v[e] - m1);
        }
        int s2 = -1; float m2 = -INFINITY;
        #pragma unroll
        for (int e = 0; e < Ed; e++) if (e != s1 && v[e] > m2) { m2 = v[e]; s2 = e; }
        float Z2 = 0.0f;
        #pragma unroll
        for (int e = 0; e < Ed; e++) {
            if (e == s1) continue;
            float factor = fmaxf(fabsf(v[e]), m2);
            if (!((m2 - v[e]) / factor > 0.02f)) Z2 += expf(v[e] - m2);
        }
        g_sel [t * 2 + 0] = s1;        g_sel [t * 2 + 1] = s2;
        g_mult[t * 2 + 0] = 1.0f / Z1; g_mult[t * 2 + 1] = 1.0f / Z2;
    }
}

// ---------------- kernel 2: scatter ----------------
__global__ void scatter_kernel() {
    int t = blockIdx.x * 256 + threadIdx.x;
    if (t >= T) return;
    #pragma unroll
    for (int k = 0; k < 2; k++) {
        int e = g_sel[t * 2 + k];
        int p = atomicAdd(&g_cnt[e], 1);
        g_tok[e * T + p] = t;
        g_pw [e * T + p] = g_mult[t * 2 + k];
    }
}

// ---------------- kernel 3: ffn1 (fp16 wmma, dual GEMM) ---------------------
// grid (Fd/BN=32, Ed*8=64), 256 threads (8 warps, 4m x 2n), warp 32x32 dual
__global__ __launch_bounds__(256, 2) void ffn1_kernel()
{
    extern __shared__ char sm[];
    int e   = blockIdx.y >> 3;
    int mt  = blockIdx.y & 7;
    int cnt = g_cnt[e];
    int m0  = mt * BM;
    if (m0 >= cnt) return;
    int f0  = blockIdx.x * BN;

    int* toks = (int*)sm;
    int tid = threadIdx.x;
    if (tid < BM) {
        int i = m0 + tid;
        toks[tid] = (i < cnt) ? g_tok[e * T + i] : g_tok[e * T];
    }
    __syncthreads();

    int ar0 = tid >> 2;                 // 0..63
    int aq  = (tid & 3) * 8;            // half offset (16B chunks)
    uint32_t soA0 = (uint32_t)ar0 * RB + (tid & 3) * 16;
    uint32_t soA1 = soA0 + 64 * RB;
    uint32_t soB  = soA0;

    const __half* w1e = g_w1h + (size_t)e * Fd * Hd;
    const __half* w3e = g_w3h + (size_t)e * Fd * Hd;
    const __half* ag0 = g_xh + (size_t)toks[ar0]      * Hd + aq;
    const __half* ag1 = g_xh + (size_t)toks[ar0 + 64] * Hd + aq;
    const __half* b1g = w1e + (size_t)(f0 + ar0) * Hd + aq;
    const __half* b3g = w3e + (size_t)(f0 + ar0) * Hd + aq;

    char* smA  = sm + F1_A;
    char* smB1 = sm + F1_B1;
    char* smB3 = sm + F1_B3;

    #pragma unroll
    for (int s = 0; s < NSTAGE - 1; s++) {
        int k0 = s * BK;
        cp16(smA  + s * A_BYTES + soA0, ag0 + k0);
        cp16(smA  + s * A_BYTES + soA1, ag1 + k0);
        cp16(smB1 + s * B_BYTES + soB,  b1g + k0);
        cp16(smB3 + s * B_BYTES + soB,  b3g + k0);
        CP_COMMIT();
    }

    wmma::fragment<wmma::matrix_a, 16,16,16, __half, wmma::row_major> fa[2];
    wmma::fragment<wmma::matrix_b, 16,16,16, __half, wmma::col_major> fb1[2], fb3[2];
    wmma::fragment<wmma::accumulator, 16,16,16, float> acc1[2][2], acc3[2][2];
    #pragma unroll
    for (int i = 0; i < 2; i++)
        #pragma unroll
        for (int j = 0; j < 2; j++) { wmma::fill_fragment(acc1[i][j], 0.f); wmma::fill_fragment(acc3[i][j], 0.f); }

    int wid = tid >> 5;
    int wm  = wid >> 1;     // 0..3
    int wn  = wid & 1;      // 0..1

    int cur = 0, nxt = NSTAGE - 1;
    const int NS = Hd / BK;   // 32
    for (int s = 0; s < NS; s++) {
        CP_WAIT1();
        __syncthreads();
        if (s + NSTAGE - 1 < NS) {
            int k0 = (s + NSTAGE - 1) * BK;
            cp16(smA  + nxt * A_BYTES + soA0, ag0 + k0);
            cp16(smA  + nxt * A_BYTES + soA1, ag1 + k0);
            cp16(smB1 + nxt * B_BYTES + soB,  b1g + k0);
            cp16(smB3 + nxt * B_BYTES + soB,  b3g + k0);
        }
        CP_COMMIT();

        const __half* Ab  = (const __half*)(smA  + cur * A_BYTES);
        const __half* B1b = (const __half*)(smB1 + cur * B_BYTES);
        const __half* B3b = (const __half*)(smB3 + cur * B_BYTES);
        #pragma unroll
        for (int ks = 0; ks < BK; ks += 16) {
            wmma::load_matrix_sync(fa[0],  Ab  + (wm*32     ) * KP + ks, KP);
            wmma::load_matrix_sync(fa[1],  Ab  + (wm*32 + 16) * KP + ks, KP);
            wmma::load_matrix_sync(fb1[0], B1b + (wn*32     ) * KP + ks, KP);
            wmma::load_matrix_sync(fb1[1], B1b + (wn*32 + 16) * KP + ks, KP);
            wmma::load_matrix_sync(fb3[0], B3b + (wn*32     ) * KP + ks, KP);
            wmma::load_matrix_sync(fb3[1], B3b + (wn*32 + 16) * KP + ks, KP);
            #pragma unroll
            for (int i = 0; i < 2; i++)
                #pragma unroll
                for (int j = 0; j < 2; j++) {
                    wmma::mma_sync(acc1[i][j], fa[i], fb1[j], acc1[i][j]);
                    wmma::mma_sync(acc3[i][j], fa[i], fb3[j], acc3[i][j]);
                }
        }
        cur = (cur + 1 == NSTAGE) ? 0 : cur + 1;
        nxt = (nxt + 1 == NSTAGE) ? 0 : nxt + 1;
    }

    // epilogue: silu(h1)*h3 in registers, stage f32 tile in smem, emit half
    __syncthreads();   // stage buffers dead; reuse as pool
    float* pool = (float*)(sm + F1_A);
    #pragma unroll
    for (int i = 0; i < 2; i++)
        #pragma unroll
        for (int j = 0; j < 2; j++) {
            #pragma unroll
            for (int el = 0; el < acc1[i][j].num_elements; el++) {
                float h1 = acc1[i][j].x[el], h3 = acc3[i][j].x[el];
                acc1[i][j].x[el] = h1 / (1.0f + expf(-h1)) * h3;
            }
            wmma::store_matrix_sync(
                pool + (size_t)(wm*32 + i*16) * OPAD + wn*32 + j*16,
                acc1[i][j], OPAD, wmma::mem_row_major);
        }
    __syncthreads();

    for (int idx = tid; idx < BM * BN / 2; idx += 256) {
        int r  = idx >> 5;          // 0..127
        int c2 = idx & 31;          // half2 col 0..31
        uint32_t h = f2h2(pool[r * OPAD + 2*c2], pool[r * OPAD + 2*c2 + 1]);
        *(uint32_t*)&g_interh[((size_t)e * T + m0 + r) * Fd + f0 + 2*c2] = h;
    }
}

// ---------------- kernel 4: ffn2 (fp16 wmma, weighted atomic out) -----------
// grid (Hd/BN=16, Ed*8=64), 256 threads, warp 32x32
__global__ __launch_bounds__(256, 2) void ffn2_kernel(float* __restrict__ out)
{
    extern __shared__ char sm[];
    int e   = blockIdx.y >> 3;
    int mt  = blockIdx.y & 7;
    int cnt = g_cnt[e];
    int m0  = mt * BM;
    if (m0 >= cnt) return;
    int h0  = blockIdx.x * BN;

    int*   toks = (int*)sm;
    float* pws  = (float*)(sm + 512);
    int tid = threadIdx.x;
    if (tid < BM) {
        int i = m0 + tid;
        toks[tid] = (i < cnt) ? g_tok[e * T + i] : 0;
        pws [tid] = (i < cnt) ? g_pw [e * T + i] : 0.0f;
    }
    __syncthreads();

    int ar0 = tid >> 2;
    int aq  = (tid & 3) * 8;
    uint32_t soA0 = (uint32_t)ar0 * RB + (tid & 3) * 16;
    uint32_t soA1 = soA0 + 64 * RB;
    uint32_t soB  = soA0;

    const __half* ag0 = &g_interh[((size_t)e * T + m0 + ar0     ) * Fd + aq];
    const __half* ag1 = &g_interh[((size_t)e * T + m0 + ar0 + 64) * Fd + aq];
    const __half* bg  = g_w2h + ((size_t)e * Hd + h0 + ar0) * Fd + aq;

    char* smA = sm + F2_A;
    char* smB = sm + F2_B;

    #pragma unroll
    for (int s = 0; s < NSTAGE - 1; s++) {
        int k0 = s * BK;
        cp16(smA + s * A_BYTES + soA0, ag0 + k0);
        cp16(smA + s * A_BYTES + soA1, ag1 + k0);
        cp16(smB + s * B_BYTES + soB,  bg  + k0);
        CP_COMMIT();
    }

    wmma::fragment<wmma::matrix_a, 16,16,16, __half, wmma::row_major> fa[2];
    wmma::fragment<wmma::matrix_b, 16,16,16, __half, wmma::col_major> fb[2];
    wmma::fragment<wmma::accumulator, 16,16,16, float> acc[2][2];
    #pragma unroll
    for (int i = 0; i < 2; i++)
        #pragma unroll
        for (int j = 0; j < 2; j++) wmma::fill_fragment(acc[i][j], 0.f);

    int wid = tid >> 5;
    int wm  = wid >> 1;
    int wn  = wid & 1;

    int cur = 0, nxt = NSTAGE - 1;
    const int NS = Fd / BK;   // 64
    for (int s = 0; s < NS; s++) {
        CP_WAIT1();
        __syncthreads();
        if (s + NSTAGE - 1 < NS) {
            int k0 = (s + NSTAGE - 1) * BK;
            cp16(smA + nxt * A_BYTES + soA0, ag0 + k0);
            cp16(smA + nxt * A_BYTES + soA1, ag1 + k0);
            cp16(smB + nxt * B_BYTES + soB,  bg  + k0);
        }
        CP_COMMIT();

        const __half* Ab = (const __half*)(smA + cur * A_BYTES);
        const __half* Bb = (const __half*)(smB + cur * B_BYTES);
        #pragma unroll
        for (int ks = 0; ks < BK; ks += 16) {
            wmma::load_matrix_sync(fa[0], Ab + (wm*32     ) * KP + ks, KP);
            wmma::load_matrix_sync(fa[1], Ab + (wm*32 + 16) * KP + ks, KP);
            wmma::load_matrix_sync(fb[0], Bb + (wn*32     ) * KP + ks, KP);
            wmma::load_matrix_sync(fb[1], Bb + (wn*32 + 16) * KP + ks, KP);
            #pragma unroll
            for (int i = 0; i < 2; i++)
                #pragma unroll
                for (int j = 0; j < 2; j++)
                    wmma::mma_sync(acc[i][j], fa[i], fb[j], acc[i][j]);
        }
        cur = (cur + 1 == NSTAGE) ? 0 : cur + 1;
        nxt = (nxt + 1 == NSTAGE) ? 0 : nxt + 1;
    }

    __syncthreads();
    float* pool = (float*)(sm + F2_A);
    #pragma unroll
    for (int i = 0; i < 2; i++)
        #pragma unroll
        for (int j = 0; j < 2; j++)
            wmma::store_matrix_sync(
                pool + (size_t)(wm*32 + i*16) * OPAD + wn*32 + j*16,
                acc[i][j], OPAD, wmma::mem_row_major);
    __syncthreads();

    for (int idx = tid; idx < BM * BN; idx += 256) {
        int r = idx >> 6;
        int c = idx & 63;
        if (m0 + r < cnt)
            atomicAdd(&out[(size_t)toks[r] * Hd + h0 + c], pws[r] * pool[r * OPAD + c]);
    }
}

// ---------------- launch ----------------
extern "C" void kernel_launch(void* const* d_in, const int* in_sizes, int n_in,
                              void* d_out, int out_size)
{
    const float* x  = (const float*)d_in[0];
    const float* gw = (const float*)d_in[1];
    const float* w1 = (const float*)d_in[2];
    const float* w2 = (const float*)d_in[3];
    const float* w3 = (const float*)d_in[4];
    float* out = (float*)d_out;

    cudaFuncSetAttribute(ffn1_kernel, cudaFuncAttributeMaxDynamicSharedMemorySize, SMEM_FFN1);
    cudaFuncSetAttribute(ffn2_kernel, cudaFuncAttributeMaxDynamicSharedMemorySize, SMEM_FFN2);

    int write_logits = (out_size >= T * Hd + T * Ed) ? 1 : 0;
    float* out_logits = out + (size_t)T * Hd;

    void *d_w1h, *d_w3h, *d_w2h, *d_xh;
    cudaGetSymbolAddress(&d_w1h, g_w1h);
    cudaGetSymbolAddress(&d_w3h, g_w3h);
    cudaGetSymbolAddress(&d_w2h, g_w2h);
    cudaGetSymbolAddress(&d_xh,  g_xh);

    zero_kernel   <<<(T * Hd) / 256, 256>>>(out);
    router_kernel <<<T, 256>>>(x, gw, out_logits, write_logits);
    scatter_kernel<<<T / 256, 256>>>();

    // fp32 -> fp16 pre-convert (memory-bound)
    const int WBLK = (int)((size_t)Ed * Fd * Hd / 8 / 256);   // 8192
    cvt_h_kernel<<<(T * Hd / 8) / 256, 256>>>((const float4*)x,  (uint4*)d_xh);
    cvt_h_kernel<<<WBLK, 256>>>((const float4*)w1, (uint4*)d_w1h);
    cvt_h_kernel<<<WBLK, 256>>>((const float4*)w3, (uint4*)d_w3h);
    cvt_h_kernel<<<WBLK, 256>>>((const float4*)w2, (uint4*)d_w2h);

    dim3 g1(Fd / BN, Ed * 8);
    ffn1_kernel<<<g1, 256, SMEM_FFN1>>>();

    dim3 g2(Hd / BN, Ed * 8);
    ffn2_kernel<<<g2, 256, SMEM_FFN2>>>(out);
}